// round 1
// baseline (speedup 1.0000x reference)
#include <cuda_runtime.h>

#define Bv 8
#define Cv 128
#define Hv 128
#define Wv 128
#define KK 9
#define ROWS 16

// Scratch (no allocations allowed in kernel_launch)
__device__ float g_pooled[Bv * Cv];
__device__ float g_kern[Bv * Cv * KK];

// ---------------------------------------------------------------------------
// Kernel 1: global average pool per (b,c) plane. 1024 blocks x 256 threads.
// Each thread: 16 float4 loads (64 floats), warp+smem tree reduce.
// ---------------------------------------------------------------------------
__global__ void pool_kernel(const float* __restrict__ x) {
    const int plane = blockIdx.x;  // b*C + c
    const float4* xp = reinterpret_cast<const float4*>(x + (size_t)plane * Hv * Wv);

    float sum = 0.f;
#pragma unroll
    for (int i = 0; i < 16; i++) {
        float4 v = xp[threadIdx.x + i * 256];
        sum += (v.x + v.y) + (v.z + v.w);
    }

    __shared__ float sdata[8];
#pragma unroll
    for (int o = 16; o; o >>= 1) sum += __shfl_down_sync(0xffffffffu, sum, o);
    if ((threadIdx.x & 31) == 0) sdata[threadIdx.x >> 5] = sum;
    __syncthreads();
    if (threadIdx.x < 8) {
        sum = sdata[threadIdx.x];
#pragma unroll
        for (int o = 4; o; o >>= 1) sum += __shfl_down_sync(0xffu, sum, o);
        if (threadIdx.x == 0) g_pooled[plane] = sum * (1.f / (float)(Hv * Wv));
    }
}

// ---------------------------------------------------------------------------
// Kernel 2: fused 2-layer MLP per batch element.
//   h    = relu(pooled @ w1^T + b1)      [C]
//   kern = h @ w2^T + b2                 [C*9]
// 8 blocks x 256 threads; tiny.
// ---------------------------------------------------------------------------
__global__ void mlp_kernel(const float* __restrict__ w1, const float* __restrict__ b1,
                           const float* __restrict__ w2, const float* __restrict__ b2) {
    const int b = blockIdx.x;
    const int tid = threadIdx.x;
    __shared__ float ps[Cv];
    __shared__ float hs[Cv];

    if (tid < Cv) ps[tid] = g_pooled[b * Cv + tid];
    __syncthreads();

    if (tid < Cv) {
        float acc = b1[tid];
        const float* wr = w1 + (size_t)tid * Cv;
#pragma unroll 8
        for (int c = 0; c < Cv; c++) acc = fmaf(ps[c], wr[c], acc);
        hs[tid] = fmaxf(acc, 0.f);
    }
    __syncthreads();

    for (int o = tid; o < Cv * KK; o += blockDim.x) {
        float acc = b2[o];
        const float* wr = w2 + (size_t)o * Cv;
#pragma unroll 8
        for (int c = 0; c < Cv; c++) acc = fmaf(hs[c], wr[c], acc);
        g_kern[b * Cv * KK + o] = acc;
    }
}

// ---------------------------------------------------------------------------
// Kernel 3: dynamic depthwise 3x3 conv (cross-correlation, zero pad).
// One block per 16-row strip of one (b,c) plane: 1024*8 blocks x 128 threads.
// Smem tile (ROWS+2) x (W+2) with zero halo; register-sliding 3x3 window
// so each output needs only 3 new LDS.
// ---------------------------------------------------------------------------
__global__ void conv_kernel(const float* __restrict__ x, float* __restrict__ out) {
    const int plane = blockIdx.x >> 3;
    const int rowblk = blockIdx.x & 7;
    const int row0 = rowblk * ROWS;
    const int t = threadIdx.x;  // 0..127 (column)

    __shared__ float s[ROWS + 2][Wv + 2];

    const float* xp = x + (size_t)plane * Hv * Wv;

    // Stage input rows (with top/bottom zero halo)
#pragma unroll
    for (int r = 0; r < ROWS + 2; r++) {
        const int gr = row0 + r - 1;
        float v = (gr >= 0 && gr < Hv) ? __ldg(xp + gr * Wv + t) : 0.f;
        s[r][t + 1] = v;
    }
    // Left/right zero halo columns
    if (t < ROWS + 2) {
        s[t][0] = 0.f;
        s[t][Wv + 1] = 0.f;
    }

    // Per-plane 3x3 weights (broadcast load)
    float w[9];
#pragma unroll
    for (int p = 0; p < 9; p++) w[p] = g_kern[plane * KK + p];

    __syncthreads();

    float* op = out + (size_t)plane * Hv * Wv + (size_t)row0 * Wv + t;

    float a0 = s[0][t], a1 = s[0][t + 1], a2 = s[0][t + 2];
    float e0 = s[1][t], e1 = s[1][t + 1], e2 = s[1][t + 2];
#pragma unroll
    for (int r = 0; r < ROWS; r++) {
        const float c0 = s[r + 2][t], c1 = s[r + 2][t + 1], c2 = s[r + 2][t + 2];
        float acc = a0 * w[0];
        acc = fmaf(a1, w[1], acc);
        acc = fmaf(a2, w[2], acc);
        acc = fmaf(e0, w[3], acc);
        acc = fmaf(e1, w[4], acc);
        acc = fmaf(e2, w[5], acc);
        acc = fmaf(c0, w[6], acc);
        acc = fmaf(c1, w[7], acc);
        acc = fmaf(c2, w[8], acc);
        op[r * Wv] = acc;
        a0 = e0; a1 = e1; a2 = e2;
        e0 = c0; e1 = c1; e2 = c2;
    }
}

// ---------------------------------------------------------------------------
extern "C" void kernel_launch(void* const* d_in, const int* in_sizes, int n_in,
                              void* d_out, int out_size) {
    const float* x  = (const float*)d_in[0];
    const float* w1 = (const float*)d_in[1];
    const float* b1 = (const float*)d_in[2];
    const float* w2 = (const float*)d_in[3];
    const float* b2 = (const float*)d_in[4];
    float* out = (float*)d_out;

    pool_kernel<<<Bv * Cv, 256>>>(x);
    mlp_kernel<<<Bv, 256>>>(w1, b1, w2, b2);
    conv_kernel<<<Bv * Cv * (Hv / ROWS), 128>>>(x, out);
}

// round 2
// speedup vs baseline: 1.0172x; 1.0172x over previous
#include <cuda_runtime.h>

#define Bv 8
#define Cv 128
#define Hv 128
#define Wv 128
#define KK 9
#define ROWS 32   // rows per strip (conv)

typedef unsigned long long u64;

// Scratch (no allocations allowed in kernel_launch)
__device__ float g_pooled[Bv * Cv];
__device__ float g_kern[Bv * Cv * KK];

// ---- packed f32x2 helpers (Blackwell FFMA2 via PTX) ------------------------
__device__ __forceinline__ u64 pack2(float lo, float hi) {
    u64 r;
    asm("mov.b64 %0, {%1, %2};" : "=l"(r) : "f"(lo), "f"(hi));
    return r;
}
__device__ __forceinline__ u64 fma2(u64 a, u64 b, u64 c) {
    u64 d;
    asm("fma.rn.f32x2 %0, %1, %2, %3;" : "=l"(d) : "l"(a), "l"(b), "l"(c));
    return d;
}
__device__ __forceinline__ u64 mul2(u64 a, u64 b) {
    u64 d;
    asm("mul.rn.f32x2 %0, %1, %2;" : "=l"(d) : "l"(a), "l"(b));
    return d;
}

// ---------------------------------------------------------------------------
// Kernel 1: global average pool per (b,c) plane. 1024 blocks x 256 threads.
// ---------------------------------------------------------------------------
__global__ void pool_kernel(const float* __restrict__ x) {
    const int plane = blockIdx.x;  // b*C + c
    const float4* xp = reinterpret_cast<const float4*>(x + (size_t)plane * Hv * Wv);

    float sum = 0.f;
#pragma unroll
    for (int i = 0; i < 16; i++) {
        float4 v = xp[threadIdx.x + i * 256];
        sum += (v.x + v.y) + (v.z + v.w);
    }

    __shared__ float sdata[8];
#pragma unroll
    for (int o = 16; o; o >>= 1) sum += __shfl_down_sync(0xffffffffu, sum, o);
    if ((threadIdx.x & 31) == 0) sdata[threadIdx.x >> 5] = sum;
    __syncthreads();
    if (threadIdx.x < 8) {
        sum = sdata[threadIdx.x];
#pragma unroll
        for (int o = 4; o; o >>= 1) sum += __shfl_down_sync(0xffu, sum, o);
        if (threadIdx.x == 0) g_pooled[plane] = sum * (1.f / (float)(Hv * Wv));
    }
}

// ---------------------------------------------------------------------------
// Kernel 2: fused 2-layer MLP per batch element (tiny).
// ---------------------------------------------------------------------------
__global__ void mlp_kernel(const float* __restrict__ w1, const float* __restrict__ b1,
                           const float* __restrict__ w2, const float* __restrict__ b2) {
    const int b = blockIdx.x;
    const int tid = threadIdx.x;
    __shared__ float ps[Cv];
    __shared__ float hs[Cv];

    if (tid < Cv) ps[tid] = g_pooled[b * Cv + tid];
    __syncthreads();

    if (tid < Cv) {
        float acc = b1[tid];
        const float* wr = w1 + (size_t)tid * Cv;
#pragma unroll 8
        for (int c = 0; c < Cv; c++) acc = fmaf(ps[c], wr[c], acc);
        hs[tid] = fmaxf(acc, 0.f);
    }
    __syncthreads();

    for (int o = tid; o < Cv * KK; o += blockDim.x) {
        float acc = b2[o];
        const float* wr = w2 + (size_t)o * Cv;
#pragma unroll 8
        for (int c = 0; c < Cv; c++) acc = fmaf(hs[c], wr[c], acc);
        g_kern[b * Cv * KK + o] = acc;
    }
}

// ---------------------------------------------------------------------------
// Kernel 3: dynamic depthwise 3x3 conv using packed f32x2 FMA (FFMA2).
// Block = (64, 2): tx handles output columns (2tx, 2tx+1); ty splits the
// 32-row strip into two 16-row halves. Grid = 1024 planes * 4 strips.
// Smem tile (ROWS+2) x (W+2), zero halo. Sliding 3-row window of packed
// pairs: per output row = 2x LDS.64 + 1 pack + 9 FFMA2 + 1 STG.64.
// ---------------------------------------------------------------------------
__global__ void conv_kernel(const float* __restrict__ x, float* __restrict__ out) {
    const int plane = blockIdx.x >> 2;
    const int strip = blockIdx.x & 3;
    const int row0 = strip * ROWS;
    const int tx = threadIdx.x;            // 0..63
    const int ty = threadIdx.y;            // 0..1
    const int tid = ty * 64 + tx;          // 0..127

    __shared__ __align__(16) float s[ROWS + 2][Wv + 2];

    const float* xp = x + (size_t)plane * Hv * Wv;

    // Stage (ROWS+2) rows, column tid, with top/bottom zero halo.
#pragma unroll
    for (int r = 0; r < ROWS + 2; r++) {
        const int gr = row0 + r - 1;
        float v = (gr >= 0 && gr < Hv) ? xp[gr * Wv + tid] : 0.f;
        s[r][tid + 1] = v;
    }
    if (tid < ROWS + 2) {
        s[tid][0] = 0.f;
        s[tid][Wv + 1] = 0.f;
    }

    // Broadcast per-plane 3x3 weights, duplicated into both f32x2 lanes.
    u64 w2p[9];
#pragma unroll
    for (int p = 0; p < 9; p++) {
        const float w = g_kern[plane * KK + p];
        w2p[p] = pack2(w, w);
    }

    __syncthreads();

    // This thread's half-strip: rows [rbase, rbase+16) in smem-local space.
    const int rbase = ty * (ROWS / 2);
    float* op = out + (size_t)plane * Hv * Wv + (size_t)(row0 + rbase) * Wv + 2 * tx;

    // Packed-row loader: smem row r, columns for this thread.
    //   lo = (x[2tx-1], x[2tx])   -> tap -1 pair (direct LDS.64)
    //   hi = (x[2tx+1], x[2tx+2]) -> tap +1 pair (direct LDS.64)
    //   mid= (x[2tx],   x[2tx+1]) -> tap  0 pair (one pack)
#define LOADROW(r, m1, m0, p1)                                   \
    {                                                            \
        float2 lo = *(const float2*)&s[(r)][2 * tx];             \
        float2 hi = *(const float2*)&s[(r)][2 * tx + 2];         \
        (m1) = pack2(lo.x, lo.y);                                \
        (p1) = pack2(hi.x, hi.y);                                \
        (m0) = pack2(lo.y, hi.x);                                \
    }

    u64 a0, a1, a2, e0, e1, e2;
    LOADROW(rbase + 0, a0, a1, a2);
    LOADROW(rbase + 1, e0, e1, e2);

#pragma unroll
    for (int lr = 0; lr < ROWS / 2; lr++) {
        u64 c0, c1, c2;
        LOADROW(rbase + lr + 2, c0, c1, c2);

        u64 acc = mul2(a0, w2p[0]);
        acc = fma2(a1, w2p[1], acc);
        acc = fma2(a2, w2p[2], acc);
        acc = fma2(e0, w2p[3], acc);
        acc = fma2(e1, w2p[4], acc);
        acc = fma2(e2, w2p[5], acc);
        acc = fma2(c0, w2p[6], acc);
        acc = fma2(c1, w2p[7], acc);
        acc = fma2(c2, w2p[8], acc);

        *(u64*)(op + (size_t)lr * Wv) = acc;   // 2 output pixels, one STG.64

        a0 = e0; a1 = e1; a2 = e2;
        e0 = c0; e1 = c1; e2 = c2;
    }
#undef LOADROW
}

// ---------------------------------------------------------------------------
extern "C" void kernel_launch(void* const* d_in, const int* in_sizes, int n_in,
                              void* d_out, int out_size) {
    const float* x  = (const float*)d_in[0];
    const float* w1 = (const float*)d_in[1];
    const float* b1 = (const float*)d_in[2];
    const float* w2 = (const float*)d_in[3];
    const float* b2 = (const float*)d_in[4];
    float* out = (float*)d_out;

    pool_kernel<<<Bv * Cv, 256>>>(x);
    mlp_kernel<<<Bv, 256>>>(w1, b1, w2, b2);
    conv_kernel<<<Bv * Cv * (Hv / ROWS), dim3(64, 2)>>>(x, out);
}

// round 3
// speedup vs baseline: 2.8070x; 2.7595x over previous
#include <cuda_runtime.h>

#define Bv 8
#define Cv 128
#define Hv 128
#define Wv 128
#define KK 9
#define ROWS 32   // rows per strip (conv)

typedef unsigned long long u64;

// Scratch (no allocations allowed in kernel_launch)
__device__ float g_pooled[Bv * Cv];
__device__ float g_h[Bv * Cv];
__device__ float g_kern[Bv * Cv * KK];

// ---- packed f32x2 helpers (Blackwell FFMA2 via PTX) ------------------------
__device__ __forceinline__ u64 pack2(float lo, float hi) {
    u64 r;
    asm("mov.b64 %0, {%1, %2};" : "=l"(r) : "f"(lo), "f"(hi));
    return r;
}
__device__ __forceinline__ u64 fma2(u64 a, u64 b, u64 c) {
    u64 d;
    asm("fma.rn.f32x2 %0, %1, %2, %3;" : "=l"(d) : "l"(a), "l"(b), "l"(c));
    return d;
}
__device__ __forceinline__ u64 mul2(u64 a, u64 b) {
    u64 d;
    asm("mul.rn.f32x2 %0, %1, %2;" : "=l"(d) : "l"(a), "l"(b));
    return d;
}

// ---------------------------------------------------------------------------
// Kernel 1: global average pool per (b,c) plane. 1024 blocks x 256 threads.
// ---------------------------------------------------------------------------
__global__ void pool_kernel(const float* __restrict__ x) {
    const int plane = blockIdx.x;  // b*C + c
    const float4* xp = reinterpret_cast<const float4*>(x + (size_t)plane * Hv * Wv);

    float sum = 0.f;
#pragma unroll
    for (int i = 0; i < 16; i++) {
        float4 v = xp[threadIdx.x + i * 256];
        sum += (v.x + v.y) + (v.z + v.w);
    }

    __shared__ float sdata[8];
#pragma unroll
    for (int o = 16; o; o >>= 1) sum += __shfl_down_sync(0xffffffffu, sum, o);
    if ((threadIdx.x & 31) == 0) sdata[threadIdx.x >> 5] = sum;
    __syncthreads();
    if (threadIdx.x < 8) {
        sum = sdata[threadIdx.x];
#pragma unroll
        for (int o = 4; o; o >>= 1) sum += __shfl_down_sync(0xffu, sum, o);
        if (threadIdx.x == 0) g_pooled[plane] = sum * (1.f / (float)(Hv * Wv));
    }
}

// ---------------------------------------------------------------------------
// Kernel 2a: h = relu(pooled @ w1^T + b1), warp-per-output (coalesced w1 rows).
// Grid = 8 blocks (one per batch) x 128 threads (4 warps x 32 outputs each).
// ---------------------------------------------------------------------------
__global__ void h_kernel(const float* __restrict__ w1, const float* __restrict__ b1) {
    const int b = blockIdx.x;
    const int tid = threadIdx.x;
    const int wid = tid >> 5;
    const int lane = tid & 31;

    __shared__ float ps[Cv];
    ps[tid] = g_pooled[b * Cv + tid];
    __syncthreads();

    const float4 pv = *(const float4*)&ps[lane * 4];

#pragma unroll
    for (int i = 0; i < 32; i++) {
        const int o = wid * 32 + i;
        const float4 wv = *(const float4*)(w1 + (size_t)o * Cv + lane * 4);
        float acc = wv.x * pv.x;
        acc = fmaf(wv.y, pv.y, acc);
        acc = fmaf(wv.z, pv.z, acc);
        acc = fmaf(wv.w, pv.w, acc);
#pragma unroll
        for (int s = 16; s; s >>= 1) acc += __shfl_xor_sync(0xffffffffu, acc, s);
        if (lane == 0) g_h[b * Cv + o] = fmaxf(acc + b1[o], 0.f);
    }
}

// ---------------------------------------------------------------------------
// Kernel 2b: kern = h @ w2^T + b2, warp-per-output (coalesced w2 rows).
// 9216 outputs total; 288 blocks x 128 threads; 8 outputs per warp.
// ---------------------------------------------------------------------------
__global__ void kern_kernel(const float* __restrict__ w2, const float* __restrict__ b2) {
    const int b = blockIdx.x / 36;          // batch
    const int grp = blockIdx.x % 36;        // 32-output group within [0,1152)
    const int tid = threadIdx.x;
    const int wid = tid >> 5;
    const int lane = tid & 31;

    __shared__ float hs[Cv];
    hs[tid] = g_h[b * Cv + tid];
    __syncthreads();

    const float4 hv = *(const float4*)&hs[lane * 4];

#pragma unroll
    for (int i = 0; i < 8; i++) {
        const int o = grp * 32 + wid * 8 + i;   // [0, 1152)
        const float4 wv = *(const float4*)(w2 + (size_t)o * Cv + lane * 4);
        float acc = wv.x * hv.x;
        acc = fmaf(wv.y, hv.y, acc);
        acc = fmaf(wv.z, hv.z, acc);
        acc = fmaf(wv.w, hv.w, acc);
#pragma unroll
        for (int s = 16; s; s >>= 1) acc += __shfl_xor_sync(0xffffffffu, acc, s);
        if (lane == 0) g_kern[b * Cv * KK + o] = acc + b2[o];
    }
}

// ---------------------------------------------------------------------------
// Kernel 3: dynamic depthwise 3x3 conv using packed f32x2 FMA (FFMA2).
// (unchanged from R2)
// ---------------------------------------------------------------------------
__global__ void conv_kernel(const float* __restrict__ x, float* __restrict__ out) {
    const int plane = blockIdx.x >> 2;
    const int strip = blockIdx.x & 3;
    const int row0 = strip * ROWS;
    const int tx = threadIdx.x;            // 0..63
    const int ty = threadIdx.y;            // 0..1
    const int tid = ty * 64 + tx;          // 0..127

    __shared__ __align__(16) float s[ROWS + 2][Wv + 2];

    const float* xp = x + (size_t)plane * Hv * Wv;

#pragma unroll
    for (int r = 0; r < ROWS + 2; r++) {
        const int gr = row0 + r - 1;
        float v = (gr >= 0 && gr < Hv) ? xp[gr * Wv + tid] : 0.f;
        s[r][tid + 1] = v;
    }
    if (tid < ROWS + 2) {
        s[tid][0] = 0.f;
        s[tid][Wv + 1] = 0.f;
    }

    u64 w2p[9];
#pragma unroll
    for (int p = 0; p < 9; p++) {
        const float w = g_kern[plane * KK + p];
        w2p[p] = pack2(w, w);
    }

    __syncthreads();

    const int rbase = ty * (ROWS / 2);
    float* op = out + (size_t)plane * Hv * Wv + (size_t)(row0 + rbase) * Wv + 2 * tx;

#define LOADROW(r, m1, m0, p1)                                   \
    {                                                            \
        float2 lo = *(const float2*)&s[(r)][2 * tx];             \
        float2 hi = *(const float2*)&s[(r)][2 * tx + 2];         \
        (m1) = pack2(lo.x, lo.y);                                \
        (p1) = pack2(hi.x, hi.y);                                \
        (m0) = pack2(lo.y, hi.x);                                \
    }

    u64 a0, a1, a2, e0, e1, e2;
    LOADROW(rbase + 0, a0, a1, a2);
    LOADROW(rbase + 1, e0, e1, e2);

#pragma unroll
    for (int lr = 0; lr < ROWS / 2; lr++) {
        u64 c0, c1, c2;
        LOADROW(rbase + lr + 2, c0, c1, c2);

        u64 acc = mul2(a0, w2p[0]);
        acc = fma2(a1, w2p[1], acc);
        acc = fma2(a2, w2p[2], acc);
        acc = fma2(e0, w2p[3], acc);
        acc = fma2(e1, w2p[4], acc);
        acc = fma2(e2, w2p[5], acc);
        acc = fma2(c0, w2p[6], acc);
        acc = fma2(c1, w2p[7], acc);
        acc = fma2(c2, w2p[8], acc);

        *(u64*)(op + (size_t)lr * Wv) = acc;

        a0 = e0; a1 = e1; a2 = e2;
        e0 = c0; e1 = c1; e2 = c2;
    }
#undef LOADROW
}

// ---------------------------------------------------------------------------
extern "C" void kernel_launch(void* const* d_in, const int* in_sizes, int n_in,
                              void* d_out, int out_size) {
    const float* x  = (const float*)d_in[0];
    const float* w1 = (const float*)d_in[1];
    const float* b1 = (const float*)d_in[2];
    const float* w2 = (const float*)d_in[3];
    const float* b2 = (const float*)d_in[4];
    float* out = (float*)d_out;

    pool_kernel<<<Bv * Cv, 256>>>(x);
    h_kernel<<<Bv, 128>>>(w1, b1);
    kern_kernel<<<Bv * 36, 128>>>(w2, b2);
    conv_kernel<<<Bv * Cv * (Hv / ROWS), dim3(64, 2)>>>(x, out);
}